// round 6
// baseline (speedup 1.0000x reference)
#include <cuda_runtime.h>
#include <cuda_fp16.h>
#include <cuda_fp8.h>

// Inter_domain_loss: means -> Sinkhorn via diag scaling with G and G^T stored
// as fp8 e4m3 (33.5 MB total, truly L2-resident) -> loss fused into the final
// exact row-normalize. B=2048, N=4096, D=128 (embed weights unused).

#define NN   4096
#define BB   2048
#define EPSV 1e-5f
#define MCH  32                 // mean row chunks
#define MROWS (BB / MCH)        // 64
#define TPB  80                 // transpose smem pitch (bytes), 16B-aligned rows

// Scratch (device globals; no allocation allowed)
__device__ unsigned char d_Gq [(size_t)NN * NN];  // fp8(G+eps)      16.7 MB
__device__ unsigned char d_GqT[(size_t)NN * NN];  // fp8(G+eps)^T    16.7 MB
__device__ float d_u[NN];
__device__ float d_v[NN];
__device__ float d_meanpart[2 * MCH * NN];        // 1 MB
__device__ float d_mean_src[NN];
__device__ float d_mean_trg[NN];
__device__ float d_rowfin[NN];

// ---------------------------------------------------------------------------
// Column means of source/target [B, N].  (Run FIRST so L2 churn precedes fp8.)
__global__ __launch_bounds__(256) void k_mean_part(const float* __restrict__ src,
                                                   const float* __restrict__ trg) {
    const float* base = (blockIdx.z == 0) ? src : trg;
    int col = blockIdx.x * 1024 + threadIdx.x * 4;
    int r0  = blockIdx.y * MROWS;
    float4 acc = make_float4(0.f, 0.f, 0.f, 0.f);
#pragma unroll 4
    for (int r = r0; r < r0 + MROWS; ++r) {
        float4 g = *reinterpret_cast<const float4*>(base + (size_t)r * NN + col);
        acc.x += g.x; acc.y += g.y; acc.z += g.z; acc.w += g.w;
    }
    *reinterpret_cast<float4*>(d_meanpart + (size_t)blockIdx.z * MCH * NN
                               + (size_t)blockIdx.y * NN + col) = acc;
}

__global__ __launch_bounds__(256) void k_mean_reduce() {
    __shared__ float shA[4][64];
    __shared__ float shB[4][64];
    int c = threadIdx.x & 63;
    int s = threadIdx.x >> 6;
    int j = blockIdx.x * 64 + c;
    float s0 = 0.f, s1 = 0.f;
#pragma unroll
    for (int k = 0; k < MCH / 4; ++k) {
        int ch = s * (MCH / 4) + k;
        s0 += d_meanpart[ch * NN + j];
        s1 += d_meanpart[MCH * NN + ch * NN + j];
    }
    shA[s][c] = s0;
    shB[s][c] = s1;
    __syncthreads();
    if (s == 0) {
        float a = shA[0][c] + shA[1][c] + shA[2][c] + shA[3][c];
        float b = shB[0][c] + shB[1][c] + shB[2][c] + shB[3][c];
        d_mean_src[j] = a * (1.0f / (float)BB);
        d_mean_trg[j] = b * (1.0f / (float)BB);
    }
}

// ---------------------------------------------------------------------------
// Convert G -> fp8(G+eps) into d_Gq and (via smem transpose) d_GqT.
// Grid (64, 64); 256 threads. Thread owns 1 row x 16 cols of a 64x64 tile.
__global__ __launch_bounds__(256) void k_convert_t(const float* __restrict__ G) {
    __shared__ unsigned char sh[64 * TPB];   // sh[col * TPB + row]
    int c0 = blockIdx.x * 64;
    int r0 = blockIdx.y * 64;
    int r  = threadIdx.x >> 2;               // 0..63
    int cg = (threadIdx.x & 3) * 16;         // 0,16,32,48

    const float* gp = G + (size_t)(r0 + r) * NN + c0 + cg;
    float4 a0 = *reinterpret_cast<const float4*>(gp);
    float4 a1 = *reinterpret_cast<const float4*>(gp + 4);
    float4 a2 = *reinterpret_cast<const float4*>(gp + 8);
    float4 a3 = *reinterpret_cast<const float4*>(gp + 12);

    uint4 packed;
    __nv_fp8x2_storage_t* p = reinterpret_cast<__nv_fp8x2_storage_t*>(&packed);
    p[0] = __nv_cvt_float2_to_fp8x2(make_float2(a0.x + EPSV, a0.y + EPSV), __NV_SATFINITE, __NV_E4M3);
    p[1] = __nv_cvt_float2_to_fp8x2(make_float2(a0.z + EPSV, a0.w + EPSV), __NV_SATFINITE, __NV_E4M3);
    p[2] = __nv_cvt_float2_to_fp8x2(make_float2(a1.x + EPSV, a1.y + EPSV), __NV_SATFINITE, __NV_E4M3);
    p[3] = __nv_cvt_float2_to_fp8x2(make_float2(a1.z + EPSV, a1.w + EPSV), __NV_SATFINITE, __NV_E4M3);
    p[4] = __nv_cvt_float2_to_fp8x2(make_float2(a2.x + EPSV, a2.y + EPSV), __NV_SATFINITE, __NV_E4M3);
    p[5] = __nv_cvt_float2_to_fp8x2(make_float2(a2.z + EPSV, a2.w + EPSV), __NV_SATFINITE, __NV_E4M3);
    p[6] = __nv_cvt_float2_to_fp8x2(make_float2(a3.x + EPSV, a3.y + EPSV), __NV_SATFINITE, __NV_E4M3);
    p[7] = __nv_cvt_float2_to_fp8x2(make_float2(a3.z + EPSV, a3.w + EPSV), __NV_SATFINITE, __NV_E4M3);

    // row-major store
    *reinterpret_cast<uint4*>(d_Gq + (size_t)(r0 + r) * NN + c0 + cg) = packed;

    // scatter transposed into smem
    const unsigned char* pb = reinterpret_cast<const unsigned char*>(&packed);
#pragma unroll
    for (int k = 0; k < 16; ++k) sh[(cg + k) * TPB + r] = pb[k];
    __syncthreads();

    // write-out: thread owns output row (c0 + r), bytes [r0+cg .. +16)
    uint4 q = *reinterpret_cast<const uint4*>(sh + r * TPB + cg);
    *reinterpret_cast<uint4*>(d_GqT + (size_t)(c0 + r) * NN + r0 + cg) = q;
}

// ---------------------------------------------------------------------------
__device__ __forceinline__ float block_reduce_256(float acc) {
    __shared__ float sh[8];
    int tid = threadIdx.x;
#pragma unroll
    for (int off = 16; off; off >>= 1) acc += __shfl_down_sync(0xffffffffu, acc, off);
    if ((tid & 31) == 0) sh[tid >> 5] = acc;
    __syncthreads();
    float a = 0.f;
    if (tid < 8) {
        a = sh[tid];
#pragma unroll
        for (int off = 4; off; off >>= 1) a += __shfl_down_sync(0xffu, a, off);
    }
    __syncthreads();
    return a;  // valid at tid==0
}

__device__ __forceinline__ void fp8x16_to_f32(const uint4& raw, float* f) {
    const __nv_fp8x2_storage_t* f8 = reinterpret_cast<const __nv_fp8x2_storage_t*>(&raw);
#pragma unroll
    for (int k = 0; k < 8; ++k) {
        __half2_raw hr = __nv_cvt_fp8x2_to_halfraw2(f8[k], __NV_E4M3);
        float2 t = __half22float2(*reinterpret_cast<__half2*>(&hr));
        f[2 * k] = t.x;
        f[2 * k + 1] = t.y;
    }
}

// v_j = 1 / sum_i GqT[j][i] * (use_u ? u[i] : 1).  Block per row; 16 elems/thread.
__global__ __launch_bounds__(256) void k_vT(int use_u) {
    int row = blockIdx.x;
    int i   = threadIdx.x * 16;
    uint4 raw = *reinterpret_cast<const uint4*>(d_GqT + (size_t)row * NN + i);
    float f[16];
    fp8x16_to_f32(raw, f);
    float acc = 0.f;
    if (use_u) {
#pragma unroll
        for (int q = 0; q < 4; ++q) {
            float4 u = *reinterpret_cast<const float4*>(d_u + i + q * 4);
            acc += f[4 * q] * u.x + f[4 * q + 1] * u.y
                 + f[4 * q + 2] * u.z + f[4 * q + 3] * u.w;
        }
    } else {
#pragma unroll
        for (int k = 0; k < 16; ++k) acc += f[k];
    }
    float tot = block_reduce_256(acc);
    if (threadIdx.x == 0) d_v[row] = 1.0f / tot;
}

// u_i = 1 / sum_j Gq[i][j] * v[j].  Block per row; 16 elems/thread.
__global__ __launch_bounds__(256) void k_u() {
    int row = blockIdx.x;
    int i   = threadIdx.x * 16;
    uint4 raw = *reinterpret_cast<const uint4*>(d_Gq + (size_t)row * NN + i);
    float f[16];
    fp8x16_to_f32(raw, f);
    float acc = 0.f;
#pragma unroll
    for (int q = 0; q < 4; ++q) {
        float4 v = *reinterpret_cast<const float4*>(d_v + i + q * 4);
        acc += f[4 * q] * v.x + f[4 * q + 1] * v.y
             + f[4 * q + 2] * v.z + f[4 * q + 3] * v.w;
    }
    float tot = block_reduce_256(acc);
    if (threadIdx.x == 0) d_u[row] = 1.0f / tot;
}

// Final exact row-normalize fused with loss:
// rowfin_i = (sum_j |mt_i - ms_j| Gq_ij v_j) / (sum_j Gq_ij v_j).
__global__ __launch_bounds__(256) void k_rowsum_final() {
    int row = blockIdx.x;
    int i   = threadIdx.x * 16;
    float mt = d_mean_trg[row];
    uint4 raw = *reinterpret_cast<const uint4*>(d_Gq + (size_t)row * NN + i);
    float f[16];
    fp8x16_to_f32(raw, f);
    float acc_t = 0.f, acc_w = 0.f;
#pragma unroll
    for (int q = 0; q < 4; ++q) {
        float4 v = *reinterpret_cast<const float4*>(d_v + i + q * 4);
        float4 m = *reinterpret_cast<const float4*>(d_mean_src + i + q * 4);
        float gv0 = f[4 * q] * v.x,     gv1 = f[4 * q + 1] * v.y;
        float gv2 = f[4 * q + 2] * v.z, gv3 = f[4 * q + 3] * v.w;
        acc_t += gv0 + gv1 + gv2 + gv3;
        acc_w += fabsf(mt - m.x) * gv0 + fabsf(mt - m.y) * gv1
               + fabsf(mt - m.z) * gv2 + fabsf(mt - m.w) * gv3;
    }
    float t = block_reduce_256(acc_t);
    float w = block_reduce_256(acc_w);
    if (threadIdx.x == 0) d_rowfin[row] = w / t;
}

__global__ __launch_bounds__(256) void k_final_reduce(float* __restrict__ out) {
    float acc = 0.f;
#pragma unroll
    for (int i = threadIdx.x; i < NN; i += 256) acc += d_rowfin[i];
    float tot = block_reduce_256(acc);
    if (threadIdx.x == 0) out[0] = tot;
}

// ---------------------------------------------------------------------------
extern "C" void kernel_launch(void* const* d_in, const int* in_sizes, int n_in,
                              void* d_out, int out_size) {
    (void)in_sizes; (void)n_in; (void)out_size;
    const float* src = (const float*)d_in[0];
    const float* trg = (const float*)d_in[1];
    const float* G   = (const float*)d_in[2];
    float* out = (float*)d_out;

    // means first: their 67 MB stream must not evict the fp8 arrays
    k_mean_part<<<dim3(4, MCH, 2), 256>>>(src, trg);
    k_mean_reduce<<<64, 256>>>();

    k_convert_t<<<dim3(64, 64), 256>>>(G);   // Gq + GqT (fp8, stays in L2)

    k_vT<<<NN, 256>>>(0);                    // v1 (col normalize, u0 = 1)
    k_u <<<NN, 256>>>();                     // u1 (row normalize)
    k_vT<<<NN, 256>>>(1);                    // v2 (col normalize)
    k_rowsum_final<<<NN, 256>>>();           // exact row-norm + loss
    k_final_reduce<<<1, 256>>>(out);
}

// round 7
// speedup vs baseline: 1.8138x; 1.8138x over previous
#include <cuda_runtime.h>
#include <cuda_fp16.h>
#include <cuda_fp8.h>

// Inter_domain_loss as ONE persistent kernel.
// 128 CTAs, each holds 32 rows of fp8(G+eps) in SMEM (128 KB). G/src/trg are
// read from DRAM exactly once; all Sinkhorn passes run from SMEM. Cross-CTA
// reductions via small global partials + hand-rolled grid barriers (all CTAs
// resident: 1 CTA/SM, 128 <= 148 SMs).
// B=2048, N=4096. Math = 2 reference Sinkhorn iterations (converged; R6
// validated fp8 at rel_err 2.7e-6).

#define NN      4096
#define BB      2048
#define EPSV    1e-5f
#define NCTA    128
#define RPC     32            // G rows per CTA
#define MRPC    16            // src/trg rows per CTA
#define THREADS 256

// smem layout (dynamic)
#define SM_G8   0                          // 32*4096 fp8 = 131072
#define SM_VEC  131072                     // 4096 floats = 16384
#define SM_MS   (131072 + 16384)           // 4096 floats = 16384
#define SM_U    (131072 + 32768)           // 32 floats
#define SM_W    (131072 + 32768 + 128)     // 8 floats
#define SM_TOT  (131072 + 32768 + 128 + 32)

// Global scratch
__device__ float d_colpart[NCTA * NN];     // 2 MB
__device__ float d_meanpartS[NCTA * NN];   // 2 MB
__device__ float d_meanpartT[NCTA * NN];   // 2 MB
__device__ float d_v[NN];
__device__ float d_mean_src[NN];
__device__ float d_mean_trg[NN];
__device__ float d_ctapart[NCTA];
__device__ unsigned d_barcnt = 0;
__device__ unsigned d_bargen = 0;

// ---------------------------------------------------------------------------
__device__ __forceinline__ void grid_barrier() {
    __syncthreads();
    if (threadIdx.x == 0) {
        __threadfence();
        unsigned gen = atomicAdd(&d_bargen, 0u);   // release only after ALL arrive,
        unsigned old = atomicAdd(&d_barcnt, 1u);   // so gen is stable pre-arrive
        if (old == NCTA - 1) {
            atomicExch(&d_barcnt, 0u);             // reset before release
            atomicAdd(&d_bargen, 1u);
        } else {
            while (atomicAdd(&d_bargen, 0u) == gen) __nanosleep(64);
        }
    }
    __syncthreads();
}

__device__ __forceinline__ void fp8x4_to_f32(unsigned raw, float* f) {
    __half2_raw h0 = __nv_cvt_fp8x2_to_halfraw2((__nv_fp8x2_storage_t)(raw & 0xFFFFu), __NV_E4M3);
    __half2_raw h1 = __nv_cvt_fp8x2_to_halfraw2((__nv_fp8x2_storage_t)(raw >> 16), __NV_E4M3);
    float2 a = __half22float2(*reinterpret_cast<__half2*>(&h0));
    float2 b = __half22float2(*reinterpret_cast<__half2*>(&h1));
    f[0] = a.x; f[1] = a.y; f[2] = b.x; f[3] = b.y;
}

// ---------------------------------------------------------------------------
__global__ __launch_bounds__(THREADS, 1)
void k_fused(const float* __restrict__ src, const float* __restrict__ trg,
             const float* __restrict__ G, float* __restrict__ out) {
    extern __shared__ unsigned char smem[];
    unsigned char* g8  = smem + SM_G8;
    float*         vec = reinterpret_cast<float*>(smem + SM_VEC);
    float*         msm = reinterpret_cast<float*>(smem + SM_MS);
    float*         ush = reinterpret_cast<float*>(smem + SM_U);
    float*         wsc = reinterpret_cast<float*>(smem + SM_W);

    const int b  = blockIdx.x;
    const int t  = threadIdx.x;
    const int c  = t * 16;              // this thread's 16-column home slice
    const int r0 = b * RPC;
    const int w  = t >> 5, l = t & 31;

    // ===== P0: load G slice -> fp8 smem, colsum0 partials; mean partials =====
    {
        float acc[16];
#pragma unroll
        for (int k = 0; k < 16; ++k) acc[k] = 0.f;
        for (int r = 0; r < RPC; ++r) {
            const float* gp = G + (size_t)(r0 + r) * NN + c;
            float4 a0 = *reinterpret_cast<const float4*>(gp);
            float4 a1 = *reinterpret_cast<const float4*>(gp + 4);
            float4 a2 = *reinterpret_cast<const float4*>(gp + 8);
            float4 a3 = *reinterpret_cast<const float4*>(gp + 12);
            float e[16] = {a0.x + EPSV, a0.y + EPSV, a0.z + EPSV, a0.w + EPSV,
                           a1.x + EPSV, a1.y + EPSV, a1.z + EPSV, a1.w + EPSV,
                           a2.x + EPSV, a2.y + EPSV, a2.z + EPSV, a2.w + EPSV,
                           a3.x + EPSV, a3.y + EPSV, a3.z + EPSV, a3.w + EPSV};
            uint4 packed;
            __nv_fp8x2_storage_t* p = reinterpret_cast<__nv_fp8x2_storage_t*>(&packed);
#pragma unroll
            for (int k = 0; k < 8; ++k) {
                p[k] = __nv_cvt_float2_to_fp8x2(make_float2(e[2 * k], e[2 * k + 1]),
                                                __NV_SATFINITE, __NV_E4M3);
                acc[2 * k]     += e[2 * k];
                acc[2 * k + 1] += e[2 * k + 1];
            }
            *reinterpret_cast<uint4*>(g8 + r * NN + c) = packed;
        }
        float* dst = d_colpart + (size_t)b * NN + c;
#pragma unroll
        for (int q = 0; q < 4; ++q)
            *reinterpret_cast<float4*>(dst + 4 * q) =
                make_float4(acc[4 * q], acc[4 * q + 1], acc[4 * q + 2], acc[4 * q + 3]);

        // mean partials over this CTA's 16 rows of src and trg
        float accS[16], accT[16];
#pragma unroll
        for (int k = 0; k < 16; ++k) { accS[k] = 0.f; accT[k] = 0.f; }
        int m0 = b * MRPC;
        for (int r = 0; r < MRPC; ++r) {
            const float* sp = src + (size_t)(m0 + r) * NN + c;
            const float* tp = trg + (size_t)(m0 + r) * NN + c;
#pragma unroll
            for (int q = 0; q < 4; ++q) {
                float4 sv = *reinterpret_cast<const float4*>(sp + 4 * q);
                float4 tv = *reinterpret_cast<const float4*>(tp + 4 * q);
                accS[4 * q] += sv.x; accS[4 * q + 1] += sv.y; accS[4 * q + 2] += sv.z; accS[4 * q + 3] += sv.w;
                accT[4 * q] += tv.x; accT[4 * q + 1] += tv.y; accT[4 * q + 2] += tv.z; accT[4 * q + 3] += tv.w;
            }
        }
        float* dS = d_meanpartS + (size_t)b * NN + c;
        float* dT = d_meanpartT + (size_t)b * NN + c;
#pragma unroll
        for (int q = 0; q < 4; ++q) {
            *reinterpret_cast<float4*>(dS + 4 * q) =
                make_float4(accS[4 * q], accS[4 * q + 1], accS[4 * q + 2], accS[4 * q + 3]);
            *reinterpret_cast<float4*>(dT + 4 * q) =
                make_float4(accT[4 * q], accT[4 * q + 1], accT[4 * q + 2], accT[4 * q + 3]);
        }
    }
    grid_barrier();

    // ===== P1: reduce colsum0 -> v1; reduce means =====
    {
        int col = b * 32 + (t >> 3);
        int s   = t & 7;
        float sum = 0.f, sS = 0.f, sT = 0.f;
#pragma unroll
        for (int k = 0; k < 16; ++k) {
            int cta = s * 16 + k;
            sum += __ldcg(d_colpart   + (size_t)cta * NN + col);
            sS  += __ldcg(d_meanpartS + (size_t)cta * NN + col);
            sT  += __ldcg(d_meanpartT + (size_t)cta * NN + col);
        }
#pragma unroll
        for (int off = 4; off; off >>= 1) {
            sum += __shfl_down_sync(0xffffffffu, sum, off, 8);
            sS  += __shfl_down_sync(0xffffffffu, sS,  off, 8);
            sT  += __shfl_down_sync(0xffffffffu, sT,  off, 8);
        }
        if (s == 0) {
            d_v[col]        = 1.0f / sum;
            d_mean_src[col] = sS * (1.0f / (float)BB);
            d_mean_trg[col] = sT * (1.0f / (float)BB);
        }
    }
    grid_barrier();

    // ===== P2: u1 per row (warp/row), then colsum(u1) partials =====
    {
#pragma unroll
        for (int q = 0; q < 4; ++q)
            *reinterpret_cast<float4*>(vec + c + 4 * q) = __ldcg(
                reinterpret_cast<const float4*>(d_v + c + 4 * q));
        __syncthreads();

        for (int rr = 0; rr < 4; ++rr) {
            int r = w + rr * 8;
            const unsigned char* grow = g8 + r * NN;
            float a = 0.f;
#pragma unroll 8
            for (int k = 0; k < 32; ++k) {
                int j = l * 4 + k * 128;                  // conflict-free 4-elem stride
                unsigned raw = *reinterpret_cast<const unsigned*>(grow + j);
                float f[4];
                fp8x4_to_f32(raw, f);
                float4 vv = *reinterpret_cast<const float4*>(vec + j);
                a += f[0] * vv.x + f[1] * vv.y + f[2] * vv.z + f[3] * vv.w;
            }
#pragma unroll
            for (int off = 16; off; off >>= 1) a += __shfl_down_sync(0xffffffffu, a, off);
            if (l == 0) ush[r] = 1.0f / a;
        }
        __syncthreads();

        float acc[16];
#pragma unroll
        for (int k = 0; k < 16; ++k) acc[k] = 0.f;
        for (int r = 0; r < RPC; ++r) {
            float u = ush[r];
            uint4 raw = *reinterpret_cast<const uint4*>(g8 + r * NN + c);
            const unsigned* rw = reinterpret_cast<const unsigned*>(&raw);
#pragma unroll
            for (int q = 0; q < 4; ++q) {
                float f[4];
                fp8x4_to_f32(rw[q], f);
                acc[4 * q]     += u * f[0];
                acc[4 * q + 1] += u * f[1];
                acc[4 * q + 2] += u * f[2];
                acc[4 * q + 3] += u * f[3];
            }
        }
        float* dst = d_colpart + (size_t)b * NN + c;
#pragma unroll
        for (int q = 0; q < 4; ++q)
            *reinterpret_cast<float4*>(dst + 4 * q) =
                make_float4(acc[4 * q], acc[4 * q + 1], acc[4 * q + 2], acc[4 * q + 3]);
    }
    grid_barrier();

    // ===== P3: reduce -> v2 =====
    {
        int col = b * 32 + (t >> 3);
        int s   = t & 7;
        float sum = 0.f;
#pragma unroll
        for (int k = 0; k < 16; ++k)
            sum += __ldcg(d_colpart + (size_t)(s * 16 + k) * NN + col);
#pragma unroll
        for (int off = 4; off; off >>= 1) sum += __shfl_down_sync(0xffffffffu, sum, off, 8);
        if (s == 0) d_v[col] = 1.0f / sum;
    }
    grid_barrier();

    // ===== P4: per-row exact row-normalize + loss; CTA partial =====
    {
#pragma unroll
        for (int q = 0; q < 4; ++q) {
            *reinterpret_cast<float4*>(vec + c + 4 * q) = __ldcg(
                reinterpret_cast<const float4*>(d_v + c + 4 * q));
            *reinterpret_cast<float4*>(msm + c + 4 * q) = __ldcg(
                reinterpret_cast<const float4*>(d_mean_src + c + 4 * q));
        }
        __syncthreads();

        float part = 0.f;
        for (int rr = 0; rr < 4; ++rr) {
            int r = w + rr * 8;
            float mt = __ldcg(d_mean_trg + r0 + r);
            const unsigned char* grow = g8 + r * NN;
            float at = 0.f, aw = 0.f;
#pragma unroll 8
            for (int k = 0; k < 32; ++k) {
                int j = l * 4 + k * 128;
                unsigned raw = *reinterpret_cast<const unsigned*>(grow + j);
                float f[4];
                fp8x4_to_f32(raw, f);
                float4 vv = *reinterpret_cast<const float4*>(vec + j);
                float4 mm = *reinterpret_cast<const float4*>(msm + j);
                float gv0 = f[0] * vv.x, gv1 = f[1] * vv.y;
                float gv2 = f[2] * vv.z, gv3 = f[3] * vv.w;
                at += gv0 + gv1 + gv2 + gv3;
                aw += fabsf(mt - mm.x) * gv0 + fabsf(mt - mm.y) * gv1
                    + fabsf(mt - mm.z) * gv2 + fabsf(mt - mm.w) * gv3;
            }
#pragma unroll
            for (int off = 16; off; off >>= 1) {
                at += __shfl_down_sync(0xffffffffu, at, off);
                aw += __shfl_down_sync(0xffffffffu, aw, off);
            }
            if (l == 0) part += aw / at;
        }
        if (l == 0) wsc[w] = part;
        __syncthreads();
        if (t == 0) {
            float s = 0.f;
#pragma unroll
            for (int k = 0; k < 8; ++k) s += wsc[k];
            d_ctapart[b] = s;
        }
    }
    grid_barrier();

    // ===== P5: CTA 0 reduces 128 partials =====
    if (b == 0 && t < 32) {
        float s = 0.f;
#pragma unroll
        for (int k = 0; k < NCTA / 32; ++k) s += __ldcg(d_ctapart + t + 32 * k);
#pragma unroll
        for (int off = 16; off; off >>= 1) s += __shfl_down_sync(0xffffffffu, s, off);
        if (t == 0) out[0] = s;
    }
}

// ---------------------------------------------------------------------------
extern "C" void kernel_launch(void* const* d_in, const int* in_sizes, int n_in,
                              void* d_out, int out_size) {
    (void)in_sizes; (void)n_in; (void)out_size;
    const float* src = (const float*)d_in[0];
    const float* trg = (const float*)d_in[1];
    const float* G   = (const float*)d_in[2];
    float* out = (float*)d_out;

    cudaFuncSetAttribute(k_fused, cudaFuncAttributeMaxDynamicSharedMemorySize, SM_TOT);
    k_fused<<<NCTA, THREADS, SM_TOT>>>(src, trg, G, out);
}